// round 8
// baseline (speedup 1.0000x reference)
#include <cuda_runtime.h>
#include <cuda_bf16.h>
#include <cstdint>

#define ND 64
#define THREADS 384
#define WARPS_PER_CTA 12

// ---- smem layout (bytes) ----
#define BF_OFF   0                    // uint4 [6 lv][12 j][4 p][32 lane] = 147456
#define BIAS_OFF 147456               // 192 floats = 768
#define SCR_OFF  148224               // weight-staging bounce: 6144 floats = 24576 B
#define SMEM_BYTES (148224 + 24576)   // 172800

// fp32 -> (bf16 hi, bf16 lo) packed words; low half = first element
__device__ __forceinline__ void split_pk(float v0, float v1, uint32_t& hw, uint32_t& lw) {
    __nv_bfloat16 h0 = __float2bfloat16(v0), h1 = __float2bfloat16(v1);
    __nv_bfloat16 l0 = __float2bfloat16(v0 - __bfloat162float(h0));
    __nv_bfloat16 l1 = __float2bfloat16(v1 - __bfloat162float(h1));
    hw = (uint32_t)__bfloat16_as_ushort(h0) | ((uint32_t)__bfloat16_as_ushort(h1) << 16);
    lw = (uint32_t)__bfloat16_as_ushort(l0) | ((uint32_t)__bfloat16_as_ushort(l1) << 16);
}

__device__ __forceinline__ void mma4(float* c, const uint32_t* a, uint32_t b0, uint32_t b1) {
    asm volatile(
        "mma.sync.aligned.m16n8k16.row.col.f32.bf16.bf16.f32 "
        "{%0,%1,%2,%3}, {%4,%5,%6,%7}, {%8,%9}, {%0,%1,%2,%3};"
        : "+f"(c[0]), "+f"(c[1]), "+f"(c[2]), "+f"(c[3])
        : "r"(a[0]), "r"(a[1]), "r"(a[2]), "r"(a[3]), "r"(b0), "r"(b1));
}

__global__ __launch_bounds__(THREADS, 1)
void dijet_mma(const float* __restrict__ x, const float* __restrict__ dd,
               const float* __restrict__ W1, const float* __restrict__ b1,
               const float* __restrict__ W2, const float* __restrict__ b2,
               const float* __restrict__ W3, const float* __restrict__ b3,
               float* __restrict__ out, int n) {
    extern __shared__ char smem[];
    uint4*  Bfr  = (uint4*)(smem + BF_OFF);
    float*  bias = (float*)(smem + BIAS_OFF);
    float*  scr  = (float*)(smem + SCR_OFF);

    const int tid  = threadIdx.x;
    const int w    = tid >> 5;
    const int lane = tid & 31;
    const int g    = lane >> 2;     // row-in-frag 0..7
    const int c    = lane & 3;      // k/n sub-index

    if (tid < 64) { bias[tid] = b1[tid]; bias[64 + tid] = b2[tid]; bias[128 + tid] = b3[tid]; }

    // ==== stage weights once: fp32 [o][i][k] -> bf16 hi/lo fragments ====
    {
        const float* Wg[3] = {W1, W2, W3};
        for (int l = 0; l < 3; ++l) {
            for (int oh = 0; oh < 2; ++oh) {
                __syncthreads();
                const float4* src = (const float4*)(Wg[l] + oh * 32 * 192);
                float4* dst = (float4*)scr;
                for (int i4 = tid; i4 < 1536; i4 += THREADS) dst[i4] = src[i4];
                __syncthreads();
#pragma unroll
                for (int q = 0; q < 2; ++q) {
                    int cmb = w * 2 + q;            // 0..23
                    int j = cmb >> 1, pp = cmb & 1, p = oh * 2 + pp;
                    int nl0 = pp * 16 + g, nl1 = nl0 + 8;
                    int k0 = j * 16 + 2 * c;
                    int blk = k0 >> 6, i0 = k0 & 63;
                    const float* s0p = scr + nl0 * 192 + blk;
                    const float* s1p = scr + nl1 * 192 + blk;
                    uint32_t h0, l0, h1, l1, h2, l2, h3, l3;
                    split_pk(s0p[i0 * 3],       s0p[(i0 + 1) * 3], h0, l0);
                    split_pk(s0p[(i0 + 8) * 3], s0p[(i0 + 9) * 3], h1, l1);
                    split_pk(s1p[i0 * 3],       s1p[(i0 + 1) * 3], h2, l2);
                    split_pk(s1p[(i0 + 8) * 3], s1p[(i0 + 9) * 3], h3, l3);
                    Bfr[(((l * 2 + 0) * 12 + j) * 4 + p) * 32 + lane] = make_uint4(h0, h1, h2, h3);
                    Bfr[(((l * 2 + 1) * 12 + j) * 4 + p) * 32 + lane] = make_uint4(l0, l1, l2, l3);
                }
            }
        }
        __syncthreads();   // last barrier: Bfr/bias read-only from here on
    }

    const long rmax   = (long)n * 6;
    const long nwt    = (rmax + 15) / 16;                 // 16-row warp-tiles
    const long gw0    = (long)blockIdx.x * WARPS_PER_CTA + w;
    const long stride = (long)gridDim.x * WARPS_PER_CTA;

    // ==== each warp free-runs its own tile stream (no inter-warp sync) ====
    for (long t = gw0; t < nwt; t += stride) {
        const long r0 = t * 16 + g;
        const long r1 = r0 + 8;
        const bool v0 = r0 < rmax, v1 = r1 < rmax;
        const int  sa0 = (int)(r0 / 6), sl0 = (int)(r0 - (long)sa0 * 6);
        const int  sa1 = (int)(r1 / 6), sl1 = (int)(r1 - (long)sa1 * 6);

        uint32_t Ahx[8][4], Alx[8][4], Ahd[4][4], Ald[4][4];

        // ==== direct gmem gather -> A fragments ====
        {
            const float* px0 = x + (size_t)sa0 * 768 + 2 * sl0;
            const float* px1 = x + (size_t)sa1 * 768 + 2 * sl1;
#pragma unroll
            for (int j = 0; j < 8; ++j) {
                const int blk = j >> 2;              // 0 = xe, 1 = xo
                const int i0 = (j & 3) * 16 + 2 * c;
                const float* q0 = px0 + blk;
                const float* q1 = px1 + blk;
                float e00 = v0 ? __ldg(q0 + i0 * 12)       : 0.f;
                float e01 = v0 ? __ldg(q0 + (i0 + 1) * 12) : 0.f;
                float e02 = v0 ? __ldg(q0 + (i0 + 8) * 12) : 0.f;
                float e03 = v0 ? __ldg(q0 + (i0 + 9) * 12) : 0.f;
                float e10 = v1 ? __ldg(q1 + i0 * 12)       : 0.f;
                float e11 = v1 ? __ldg(q1 + (i0 + 1) * 12) : 0.f;
                float e12 = v1 ? __ldg(q1 + (i0 + 8) * 12) : 0.f;
                float e13 = v1 ? __ldg(q1 + (i0 + 9) * 12) : 0.f;
                split_pk(e00, e01, Ahx[j][0], Alx[j][0]);
                split_pk(e10, e11, Ahx[j][1], Alx[j][1]);
                split_pk(e02, e03, Ahx[j][2], Alx[j][2]);
                split_pk(e12, e13, Ahx[j][3], Alx[j][3]);
            }
            const float* d0p = dd + (size_t)sa0 * 384 + sl0;
            const float* d1p = dd + (size_t)sa1 * 384 + sl1;
#pragma unroll
            for (int jd = 0; jd < 4; ++jd) {
                const int i0 = jd * 16 + 2 * c;
                float e00 = v0 ? __ldg(d0p + i0 * 6)       : 0.f;
                float e01 = v0 ? __ldg(d0p + (i0 + 1) * 6) : 0.f;
                float e02 = v0 ? __ldg(d0p + (i0 + 8) * 6) : 0.f;
                float e03 = v0 ? __ldg(d0p + (i0 + 9) * 6) : 0.f;
                float e10 = v1 ? __ldg(d1p + i0 * 6)       : 0.f;
                float e11 = v1 ? __ldg(d1p + (i0 + 1) * 6) : 0.f;
                float e12 = v1 ? __ldg(d1p + (i0 + 8) * 6) : 0.f;
                float e13 = v1 ? __ldg(d1p + (i0 + 9) * 6) : 0.f;
                split_pk(e00, e01, Ahd[jd][0], Ald[jd][0]);
                split_pk(e10, e11, Ahd[jd][1], Ald[jd][1]);
                split_pk(e02, e03, Ahd[jd][2], Ald[jd][2]);
                split_pk(e12, e13, Ahd[jd][3], Ald[jd][3]);
            }
        }

        float acc[8][4];
#pragma unroll
        for (int nt = 0; nt < 8; ++nt)
#pragma unroll
            for (int e = 0; e < 4; ++e) acc[nt][e] = 0.f;

        // ==== 3 chained layers ====
#pragma unroll
        for (int l = 0; l < 3; ++l) {
#pragma unroll
            for (int j = 0; j < 12; ++j) {
                const uint32_t* Ah = (j < 8) ? Ahx[j] : Ahd[j - 8];
                const uint32_t* Al = (j < 8) ? Alx[j] : Ald[j - 8];
                const uint4* bhp = Bfr + (((l * 2 + 0) * 12 + j) * 4) * 32 + lane;
                const uint4* blp = Bfr + (((l * 2 + 1) * 12 + j) * 4) * 32 + lane;
#pragma unroll
                for (int p = 0; p < 4; ++p) {
                    uint4 bh = bhp[p * 32];
                    uint4 bl = blp[p * 32];
                    mma4(acc[2 * p],     Ah, bh.x, bh.y);
                    mma4(acc[2 * p + 1], Ah, bh.z, bh.w);
                    mma4(acc[2 * p],     Ah, bl.x, bl.y);
                    mma4(acc[2 * p + 1], Ah, bl.z, bl.w);
                    mma4(acc[2 * p],     Al, bh.x, bh.y);
                    mma4(acc[2 * p + 1], Al, bh.z, bh.w);
                }
            }
            if (l < 2) {
                // D -> next-layer d fragments, register-local (o dim == next k dim)
#pragma unroll
                for (int jd = 0; jd < 4; ++jd) {
                    const int o0 = jd * 16 + 2 * c;
                    float bb0 = bias[l * 64 + o0],     bb1 = bias[l * 64 + o0 + 1];
                    float bb8 = bias[l * 64 + o0 + 8], bb9 = bias[l * 64 + o0 + 9];
                    float t0 = fmaxf(acc[2 * jd][0] + bb0, 0.f);
                    float t1 = fmaxf(acc[2 * jd][1] + bb1, 0.f);
                    float t2 = fmaxf(acc[2 * jd][2] + bb0, 0.f);
                    float t3 = fmaxf(acc[2 * jd][3] + bb1, 0.f);
                    float u0 = fmaxf(acc[2 * jd + 1][0] + bb8, 0.f);
                    float u1 = fmaxf(acc[2 * jd + 1][1] + bb9, 0.f);
                    float u2 = fmaxf(acc[2 * jd + 1][2] + bb8, 0.f);
                    float u3 = fmaxf(acc[2 * jd + 1][3] + bb9, 0.f);
                    split_pk(t0, t1, Ahd[jd][0], Ald[jd][0]);
                    split_pk(t2, t3, Ahd[jd][1], Ald[jd][1]);
                    split_pk(u0, u1, Ahd[jd][2], Ald[jd][2]);
                    split_pk(u2, u3, Ahd[jd][3], Ald[jd][3]);
#pragma unroll
                    for (int e = 0; e < 4; ++e) {
                        acc[2 * jd][e] = 0.f;
                        acc[2 * jd + 1][e] = 0.f;
                    }
                }
            }
        }

        // ==== final epilogue: relu(D + b3 + d1) -> gmem ====
        {
            const size_t base0 = (size_t)sa0 * 384 + sl0;
            const size_t base1 = (size_t)sa1 * 384 + sl1;
#pragma unroll
            for (int nt = 0; nt < 8; ++nt) {
                const int o0 = nt * 8 + 2 * c;
                const float bb0 = bias[128 + o0], bb1 = bias[128 + o0 + 1];
                if (v0) {
                    size_t a00 = base0 + (size_t)o0 * 6, a01 = a00 + 6;
                    out[a00] = fmaxf(acc[nt][0] + bb0 + dd[a00], 0.f);
                    out[a01] = fmaxf(acc[nt][1] + bb1 + dd[a01], 0.f);
                }
                if (v1) {
                    size_t a10 = base1 + (size_t)o0 * 6, a11 = a10 + 6;
                    out[a10] = fmaxf(acc[nt][2] + bb0 + dd[a10], 0.f);
                    out[a11] = fmaxf(acc[nt][3] + bb1 + dd[a11], 0.f);
                }
            }
        }
    }
}

extern "C" void kernel_launch(void* const* d_in, const int* in_sizes, int n_in,
                              void* d_out, int out_size) {
    const float* x  = (const float*)d_in[0];
    const float* dd = (const float*)d_in[1];
    const float* W1 = (const float*)d_in[2];
    const float* b1 = (const float*)d_in[3];
    const float* W2 = (const float*)d_in[4];
    const float* b2 = (const float*)d_in[5];
    const float* W3 = (const float*)d_in[6];
    const float* b3 = (const float*)d_in[7];
    float* out = (float*)d_out;

    const int n = in_sizes[0] / (ND * 12);

    int sms = 148;
    cudaDeviceGetAttribute(&sms, cudaDevAttrMultiProcessorCount, 0);
    cudaFuncSetAttribute(dijet_mma, cudaFuncAttributeMaxDynamicSharedMemorySize, SMEM_BYTES);

    dijet_mma<<<sms, THREADS, SMEM_BYTES>>>(x, dd, W1, b1, W2, b2, W3, b3, out, n);
}

// round 9
// speedup vs baseline: 1.1030x; 1.1030x over previous
#include <cuda_runtime.h>
#include <cuda_bf16.h>
#include <cstdint>

#define ND 64
#define THREADS 384
#define TILE_R 192           // rows per CTA tile (12 warps x m16)

// ---- smem layout (bytes) ----
#define BF_OFF   0                    // uint4 [6 lv][12 j][4 p][32 lane] = 147456
#define BIAS_OFF 147456               // 192 floats = 768
#define SCR_OFF  148224               // weight-staging bounce: 6144 floats = 24576 B
#define EPI_OFF  172800               // 12 warps * 16*68 floats = 52224 B
#define SMEM_BYTES (172800 + 52224)   // 225024

// fp32 -> (bf16 hi, bf16 lo) packed words; low half = first element
__device__ __forceinline__ void split_pk(float v0, float v1, uint32_t& hw, uint32_t& lw) {
    __nv_bfloat16 h0 = __float2bfloat16(v0), h1 = __float2bfloat16(v1);
    __nv_bfloat16 l0 = __float2bfloat16(v0 - __bfloat162float(h0));
    __nv_bfloat16 l1 = __float2bfloat16(v1 - __bfloat162float(h1));
    hw = (uint32_t)__bfloat16_as_ushort(h0) | ((uint32_t)__bfloat16_as_ushort(h1) << 16);
    lw = (uint32_t)__bfloat16_as_ushort(l0) | ((uint32_t)__bfloat16_as_ushort(l1) << 16);
}

__device__ __forceinline__ void mma4(float* c, const uint32_t* a, uint32_t b0, uint32_t b1) {
    asm volatile(
        "mma.sync.aligned.m16n8k16.row.col.f32.bf16.bf16.f32 "
        "{%0,%1,%2,%3}, {%4,%5,%6,%7}, {%8,%9}, {%0,%1,%2,%3};"
        : "+f"(c[0]), "+f"(c[1]), "+f"(c[2]), "+f"(c[3])
        : "r"(a[0]), "r"(a[1]), "r"(a[2]), "r"(a[3]), "r"(b0), "r"(b1));
}

__global__ __launch_bounds__(THREADS, 1)
void dijet_mma(const float* __restrict__ x, const float* __restrict__ dd,
               const float* __restrict__ W1, const float* __restrict__ b1,
               const float* __restrict__ W2, const float* __restrict__ b2,
               const float* __restrict__ W3, const float* __restrict__ b3,
               float* __restrict__ out, int n) {
    extern __shared__ char smem[];
    uint4*  Bfr  = (uint4*)(smem + BF_OFF);
    float*  bias = (float*)(smem + BIAS_OFF);
    float*  scr  = (float*)(smem + SCR_OFF);

    const int tid  = threadIdx.x;
    const int w    = tid >> 5;
    const int lane = tid & 31;
    const int g    = lane >> 2;     // row-in-frag 0..7
    const int c    = lane & 3;      // k/n sub-index

    float* eb = (float*)(smem + EPI_OFF) + w * (16 * 68);

    if (tid < 64) { bias[tid] = b1[tid]; bias[64 + tid] = b2[tid]; bias[128 + tid] = b3[tid]; }

    // ==== stage weights once: fp32 [o][i][k] -> bf16 hi/lo fragments ====
    {
        const float* Wg[3] = {W1, W2, W3};
        for (int l = 0; l < 3; ++l) {
            for (int oh = 0; oh < 2; ++oh) {
                __syncthreads();
                const float4* src = (const float4*)(Wg[l] + oh * 32 * 192);
                float4* dst = (float4*)scr;
                for (int i4 = tid; i4 < 1536; i4 += THREADS) dst[i4] = src[i4];
                __syncthreads();
#pragma unroll
                for (int q = 0; q < 2; ++q) {
                    int cmb = w * 2 + q;            // 0..23
                    int j = cmb >> 1, pp = cmb & 1, p = oh * 2 + pp;
                    int nl0 = pp * 16 + g, nl1 = nl0 + 8;
                    int k0 = j * 16 + 2 * c;
                    int blk = k0 >> 6, i0 = k0 & 63;
                    const float* s0p = scr + nl0 * 192 + blk;
                    const float* s1p = scr + nl1 * 192 + blk;
                    uint32_t h0, l0, h1, l1, h2, l2, h3, l3;
                    split_pk(s0p[i0 * 3],       s0p[(i0 + 1) * 3], h0, l0);
                    split_pk(s0p[(i0 + 8) * 3], s0p[(i0 + 9) * 3], h1, l1);
                    split_pk(s1p[i0 * 3],       s1p[(i0 + 1) * 3], h2, l2);
                    split_pk(s1p[(i0 + 8) * 3], s1p[(i0 + 9) * 3], h3, l3);
                    Bfr[(((l * 2 + 0) * 12 + j) * 4 + p) * 32 + lane] = make_uint4(h0, h1, h2, h3);
                    Bfr[(((l * 2 + 1) * 12 + j) * 4 + p) * 32 + lane] = make_uint4(l0, l1, l2, l3);
                }
            }
        }
        __syncthreads();   // last barrier: Bfr/bias read-only from here on
    }

    const long rmax   = (long)n * 6;
    const int  ntiles = (int)((rmax + TILE_R - 1) / TILE_R);

    for (int tile = blockIdx.x; tile < ntiles; tile += gridDim.x) {
        const long base = (long)tile * TILE_R;
        const long row0 = base + w * 16;           // this warp's first row

        const long r0 = row0 + g;
        const long r1 = r0 + 8;
        const bool v0 = r0 < rmax, v1 = r1 < rmax;
        const int  sa0 = (int)(r0 / 6), sl0 = (int)(r0 - (long)sa0 * 6);
        const int  sa1 = (int)(r1 / 6), sl1 = (int)(r1 - (long)sa1 * 6);

        uint32_t Ahx[8][4], Alx[8][4], Ahd[4][4], Ald[4][4];

        // ==== direct gmem gather -> A fragments (x via float2: xe,xo adjacent) ====
        {
            const float* px0 = x + (size_t)sa0 * 768 + 2 * sl0;
            const float* px1 = x + (size_t)sa1 * 768 + 2 * sl1;
            const float2 z2 = make_float2(0.f, 0.f);
#pragma unroll
            for (int j = 0; j < 4; ++j) {
                const int i0 = j * 16 + 2 * c;
                float2 p00 = v0 ? __ldg((const float2*)(px0 + i0 * 12))       : z2;
                float2 p01 = v0 ? __ldg((const float2*)(px0 + (i0 + 1) * 12)) : z2;
                float2 p02 = v0 ? __ldg((const float2*)(px0 + (i0 + 8) * 12)) : z2;
                float2 p03 = v0 ? __ldg((const float2*)(px0 + (i0 + 9) * 12)) : z2;
                float2 p10 = v1 ? __ldg((const float2*)(px1 + i0 * 12))       : z2;
                float2 p11 = v1 ? __ldg((const float2*)(px1 + (i0 + 1) * 12)) : z2;
                float2 p12 = v1 ? __ldg((const float2*)(px1 + (i0 + 8) * 12)) : z2;
                float2 p13 = v1 ? __ldg((const float2*)(px1 + (i0 + 9) * 12)) : z2;
                split_pk(p00.x, p01.x, Ahx[j][0], Alx[j][0]);
                split_pk(p10.x, p11.x, Ahx[j][1], Alx[j][1]);
                split_pk(p02.x, p03.x, Ahx[j][2], Alx[j][2]);
                split_pk(p12.x, p13.x, Ahx[j][3], Alx[j][3]);
                split_pk(p00.y, p01.y, Ahx[j + 4][0], Alx[j + 4][0]);
                split_pk(p10.y, p11.y, Ahx[j + 4][1], Alx[j + 4][1]);
                split_pk(p02.y, p03.y, Ahx[j + 4][2], Alx[j + 4][2]);
                split_pk(p12.y, p13.y, Ahx[j + 4][3], Alx[j + 4][3]);
            }
            const float* d0p = dd + (size_t)sa0 * 384 + sl0;
            const float* d1p = dd + (size_t)sa1 * 384 + sl1;
#pragma unroll
            for (int jd = 0; jd < 4; ++jd) {
                const int i0 = jd * 16 + 2 * c;
                float e00 = v0 ? __ldg(d0p + i0 * 6)       : 0.f;
                float e01 = v0 ? __ldg(d0p + (i0 + 1) * 6) : 0.f;
                float e02 = v0 ? __ldg(d0p + (i0 + 8) * 6) : 0.f;
                float e03 = v0 ? __ldg(d0p + (i0 + 9) * 6) : 0.f;
                float e10 = v1 ? __ldg(d1p + i0 * 6)       : 0.f;
                float e11 = v1 ? __ldg(d1p + (i0 + 1) * 6) : 0.f;
                float e12 = v1 ? __ldg(d1p + (i0 + 8) * 6) : 0.f;
                float e13 = v1 ? __ldg(d1p + (i0 + 9) * 6) : 0.f;
                split_pk(e00, e01, Ahd[jd][0], Ald[jd][0]);
                split_pk(e10, e11, Ahd[jd][1], Ald[jd][1]);
                split_pk(e02, e03, Ahd[jd][2], Ald[jd][2]);
                split_pk(e12, e13, Ahd[jd][3], Ald[jd][3]);
            }
        }

        float acc[8][4];
#pragma unroll
        for (int nt = 0; nt < 8; ++nt)
#pragma unroll
            for (int e = 0; e < 4; ++e) acc[nt][e] = 0.f;

        // ==== 3 chained layers ====
#pragma unroll
        for (int l = 0; l < 3; ++l) {
#pragma unroll
            for (int j = 0; j < 12; ++j) {
                const uint32_t* Ah = (j < 8) ? Ahx[j] : Ahd[j - 8];
                const uint32_t* Al = (j < 8) ? Alx[j] : Ald[j - 8];
                const uint4* bhp = Bfr + (((l * 2 + 0) * 12 + j) * 4) * 32 + lane;
                const uint4* blp = Bfr + (((l * 2 + 1) * 12 + j) * 4) * 32 + lane;
#pragma unroll
                for (int p = 0; p < 4; ++p) {
                    uint4 bh = bhp[p * 32];
                    uint4 bl = blp[p * 32];
                    mma4(acc[2 * p],     Ah, bh.x, bh.y);
                    mma4(acc[2 * p + 1], Ah, bh.z, bh.w);
                    mma4(acc[2 * p],     Ah, bl.x, bl.y);
                    mma4(acc[2 * p + 1], Ah, bl.z, bl.w);
                    mma4(acc[2 * p],     Al, bh.x, bh.y);
                    mma4(acc[2 * p + 1], Al, bh.z, bh.w);
                }
            }
            if (l < 2) {
                // D -> next-layer d fragments, register-local (o dim == next k dim)
#pragma unroll
                for (int jd = 0; jd < 4; ++jd) {
                    const int o0 = jd * 16 + 2 * c;
                    float bb0 = bias[l * 64 + o0],     bb1 = bias[l * 64 + o0 + 1];
                    float bb8 = bias[l * 64 + o0 + 8], bb9 = bias[l * 64 + o0 + 9];
                    float t0 = fmaxf(acc[2 * jd][0] + bb0, 0.f);
                    float t1 = fmaxf(acc[2 * jd][1] + bb1, 0.f);
                    float t2 = fmaxf(acc[2 * jd][2] + bb0, 0.f);
                    float t3 = fmaxf(acc[2 * jd][3] + bb1, 0.f);
                    float u0 = fmaxf(acc[2 * jd + 1][0] + bb8, 0.f);
                    float u1 = fmaxf(acc[2 * jd + 1][1] + bb9, 0.f);
                    float u2 = fmaxf(acc[2 * jd + 1][2] + bb8, 0.f);
                    float u3 = fmaxf(acc[2 * jd + 1][3] + bb9, 0.f);
                    split_pk(t0, t1, Ahd[jd][0], Ald[jd][0]);
                    split_pk(t2, t3, Ahd[jd][1], Ald[jd][1]);
                    split_pk(u0, u1, Ahd[jd][2], Ald[jd][2]);
                    split_pk(u2, u3, Ahd[jd][3], Ald[jd][3]);
#pragma unroll
                    for (int e = 0; e < 4; ++e) {
                        acc[2 * jd][e] = 0.f;
                        acc[2 * jd + 1][e] = 0.f;
                    }
                }
            }
        }

        // ==== epilogue: acc+b3 -> warp smem transpose -> relu(+d1) -> gmem ====
        {
            // store D + bias into warp-private buffer [16][68]
#pragma unroll
            for (int nt = 0; nt < 8; ++nt) {
                const int o0 = nt * 8 + 2 * c;
                const float bb0 = bias[128 + o0], bb1 = bias[128 + o0 + 1];
                eb[g * 68 + o0]           = acc[nt][0] + bb0;
                eb[g * 68 + o0 + 1]       = acc[nt][1] + bb1;
                eb[(g + 8) * 68 + o0]     = acc[nt][2] + bb0;
                eb[(g + 8) * 68 + o0 + 1] = acc[nt][3] + bb1;
            }
            __syncwarp();

            const int saA = (int)(row0 / 6);
            const int saB = (int)((row0 + 15) / 6);
            for (int sa = saA; sa <= saB; ++sa) {
                if (sa >= n) break;
                const int mb = (int)((long)sa * 6 - row0);   // row index of slot 0
                if (mb >= 0 && mb + 6 <= 16) {
                    // full sample: coalesced float4 path (384 floats = 3 iters/lane)
                    const float* ddp = dd + (size_t)sa * 384;
                    float*       op  = out + (size_t)sa * 384;
#pragma unroll
                    for (int it = 0; it < 3; ++it) {
                        const int f = (it * 32 + lane) * 4;
                        float4 dv = __ldg((const float4*)(ddp + f));
                        float r[4];
#pragma unroll
                        for (int e = 0; e < 4; ++e) {
                            const int fe = f + e;
                            const int o  = fe / 6;
                            const int sl = fe - o * 6;
                            r[e] = eb[(mb + sl) * 68 + o];
                        }
                        float4 ov;
                        ov.x = fmaxf(r[0] + dv.x, 0.f);
                        ov.y = fmaxf(r[1] + dv.y, 0.f);
                        ov.z = fmaxf(r[2] + dv.z, 0.f);
                        ov.w = fmaxf(r[3] + dv.w, 0.f);
                        *(float4*)(op + f) = ov;
                    }
                } else {
                    // boundary sample: scalar path for slots inside this warp-tile
#pragma unroll
                    for (int sl = 0; sl < 6; ++sl) {
                        const int m = mb + sl;
                        if (m < 0 || m >= 16) continue;
                        if (row0 + m >= rmax) continue;
#pragma unroll
                        for (int h = 0; h < 2; ++h) {
                            const int o = lane + 32 * h;
                            const size_t a = (size_t)sa * 384 + (size_t)o * 6 + sl;
                            out[a] = fmaxf(eb[m * 68 + o] + dd[a], 0.f);
                        }
                    }
                }
            }
            __syncwarp();   // eb reused next tile
        }
    }
}

extern "C" void kernel_launch(void* const* d_in, const int* in_sizes, int n_in,
                              void* d_out, int out_size) {
    const float* x  = (const float*)d_in[0];
    const float* dd = (const float*)d_in[1];
    const float* W1 = (const float*)d_in[2];
    const float* b1 = (const float*)d_in[3];
    const float* W2 = (const float*)d_in[4];
    const float* b2 = (const float*)d_in[5];
    const float* W3 = (const float*)d_in[6];
    const float* b3 = (const float*)d_in[7];
    float* out = (float*)d_out;

    const int n = in_sizes[0] / (ND * 12);

    int sms = 148;
    cudaDeviceGetAttribute(&sms, cudaDevAttrMultiProcessorCount, 0);
    cudaFuncSetAttribute(dijet_mma, cudaFuncAttributeMaxDynamicSharedMemorySize, SMEM_BYTES);

    dijet_mma<<<sms, THREADS, SMEM_BYTES>>>(x, dd, W1, b1, W2, b2, W3, b3, out, n);
}

// round 10
// speedup vs baseline: 1.4889x; 1.3499x over previous
#include <cuda_runtime.h>
#include <cuda_fp16.h>
#include <cstdint>

#define ND 64
#define THREADS 384
#define TILE_R 192           // rows per CTA tile (12 warps x m16)

// ---- smem layout (bytes) ----
#define BF_OFF   0                    // uint4 [3 l][12 j][4 p][32 lane] = 73728
#define BIAS_OFF 73728                // 192 floats = 768
#define SCR_OFF  74496                // weight-staging bounce: 6144 floats = 24576 B
#define EPI_OFF  99072                // 12 warps * 16*68 floats = 52224 B
#define SMEM_BYTES (99072 + 52224)    // 151296

// fp32 -> (fp16 hi, fp16 lo) packed words; A exact to ~2^-22
__device__ __forceinline__ void split_pk(float v0, float v1, uint32_t& hw, uint32_t& lw) {
    __half h0 = __float2half_rn(v0), h1 = __float2half_rn(v1);
    __half l0 = __float2half_rn(v0 - __half2float(h0));
    __half l1 = __float2half_rn(v1 - __half2float(h1));
    hw = (uint32_t)__half_as_ushort(h0) | ((uint32_t)__half_as_ushort(h1) << 16);
    lw = (uint32_t)__half_as_ushort(l0) | ((uint32_t)__half_as_ushort(l1) << 16);
}
__device__ __forceinline__ uint32_t pk_h(float v0, float v1) {
    __half h0 = __float2half_rn(v0), h1 = __float2half_rn(v1);
    return (uint32_t)__half_as_ushort(h0) | ((uint32_t)__half_as_ushort(h1) << 16);
}

__device__ __forceinline__ void mma4(float* c, const uint32_t* a, uint32_t b0, uint32_t b1) {
    asm volatile(
        "mma.sync.aligned.m16n8k16.row.col.f32.f16.f16.f32 "
        "{%0,%1,%2,%3}, {%4,%5,%6,%7}, {%8,%9}, {%0,%1,%2,%3};"
        : "+f"(c[0]), "+f"(c[1]), "+f"(c[2]), "+f"(c[3])
        : "r"(a[0]), "r"(a[1]), "r"(a[2]), "r"(a[3]), "r"(b0), "r"(b1));
}

__global__ __launch_bounds__(THREADS, 1)
void dijet_mma(const float* __restrict__ x, const float* __restrict__ dd,
               const float* __restrict__ W1, const float* __restrict__ b1,
               const float* __restrict__ W2, const float* __restrict__ b2,
               const float* __restrict__ W3, const float* __restrict__ b3,
               float* __restrict__ out, int n) {
    extern __shared__ char smem[];
    uint4*  Bfr  = (uint4*)(smem + BF_OFF);
    float*  bias = (float*)(smem + BIAS_OFF);
    float*  scr  = (float*)(smem + SCR_OFF);

    const int tid  = threadIdx.x;
    const int w    = tid >> 5;
    const int lane = tid & 31;
    const int g    = lane >> 2;     // row-in-frag 0..7
    const int c    = lane & 3;      // k/n sub-index

    float* eb = (float*)(smem + EPI_OFF) + w * (16 * 68);

    if (tid < 64) { bias[tid] = b1[tid]; bias[64 + tid] = b2[tid]; bias[128 + tid] = b3[tid]; }

    // ==== stage weights once: fp32 [o][i][k] -> single-fp16 fragments ====
    {
        const float* Wg[3] = {W1, W2, W3};
        for (int l = 0; l < 3; ++l) {
            for (int oh = 0; oh < 2; ++oh) {
                __syncthreads();
                const float4* src = (const float4*)(Wg[l] + oh * 32 * 192);
                float4* dst = (float4*)scr;
                for (int i4 = tid; i4 < 1536; i4 += THREADS) dst[i4] = src[i4];
                __syncthreads();
#pragma unroll
                for (int q = 0; q < 2; ++q) {
                    int cmb = w * 2 + q;            // 0..23
                    int j = cmb >> 1, pp = cmb & 1, p = oh * 2 + pp;
                    int nl0 = pp * 16 + g, nl1 = nl0 + 8;
                    int k0 = j * 16 + 2 * c;
                    int blk = k0 >> 6, i0 = k0 & 63;
                    const float* s0p = scr + nl0 * 192 + blk;
                    const float* s1p = scr + nl1 * 192 + blk;
                    uint32_t h0 = pk_h(s0p[i0 * 3],       s0p[(i0 + 1) * 3]);
                    uint32_t h1 = pk_h(s0p[(i0 + 8) * 3], s0p[(i0 + 9) * 3]);
                    uint32_t h2 = pk_h(s1p[i0 * 3],       s1p[(i0 + 1) * 3]);
                    uint32_t h3 = pk_h(s1p[(i0 + 8) * 3], s1p[(i0 + 9) * 3]);
                    Bfr[((l * 12 + j) * 4 + p) * 32 + lane] = make_uint4(h0, h1, h2, h3);
                }
            }
        }
        __syncthreads();   // last barrier: Bfr/bias read-only from here on
    }

    const long rmax   = (long)n * 6;
    const int  ntiles = (int)((rmax + TILE_R - 1) / TILE_R);

    for (int tile = blockIdx.x; tile < ntiles; tile += gridDim.x) {
        const long base = (long)tile * TILE_R;
        const long row0 = base + w * 16;           // this warp's first row

        const long r0 = row0 + g;
        const long r1 = r0 + 8;
        const bool v0 = r0 < rmax, v1 = r1 < rmax;
        const int  sa0 = (int)(r0 / 6), sl0 = (int)(r0 - (long)sa0 * 6);
        const int  sa1 = (int)(r1 / 6), sl1 = (int)(r1 - (long)sa1 * 6);

        uint32_t Ahx[8][4], Alx[8][4], Ahd[4][4], Ald[4][4];

        // ==== direct gmem gather -> A fragments (x via float2: xe,xo adjacent) ====
        {
            const float* px0 = x + (size_t)sa0 * 768 + 2 * sl0;
            const float* px1 = x + (size_t)sa1 * 768 + 2 * sl1;
            const float2 z2 = make_float2(0.f, 0.f);
#pragma unroll
            for (int j = 0; j < 4; ++j) {
                const int i0 = j * 16 + 2 * c;
                float2 p00 = v0 ? __ldg((const float2*)(px0 + i0 * 12))       : z2;
                float2 p01 = v0 ? __ldg((const float2*)(px0 + (i0 + 1) * 12)) : z2;
                float2 p02 = v0 ? __ldg((const float2*)(px0 + (i0 + 8) * 12)) : z2;
                float2 p03 = v0 ? __ldg((const float2*)(px0 + (i0 + 9) * 12)) : z2;
                float2 p10 = v1 ? __ldg((const float2*)(px1 + i0 * 12))       : z2;
                float2 p11 = v1 ? __ldg((const float2*)(px1 + (i0 + 1) * 12)) : z2;
                float2 p12 = v1 ? __ldg((const float2*)(px1 + (i0 + 8) * 12)) : z2;
                float2 p13 = v1 ? __ldg((const float2*)(px1 + (i0 + 9) * 12)) : z2;
                split_pk(p00.x, p01.x, Ahx[j][0], Alx[j][0]);
                split_pk(p10.x, p11.x, Ahx[j][1], Alx[j][1]);
                split_pk(p02.x, p03.x, Ahx[j][2], Alx[j][2]);
                split_pk(p12.x, p13.x, Ahx[j][3], Alx[j][3]);
                split_pk(p00.y, p01.y, Ahx[j + 4][0], Alx[j + 4][0]);
                split_pk(p10.y, p11.y, Ahx[j + 4][1], Alx[j + 4][1]);
                split_pk(p02.y, p03.y, Ahx[j + 4][2], Alx[j + 4][2]);
                split_pk(p12.y, p13.y, Ahx[j + 4][3], Alx[j + 4][3]);
            }
            const float* d0p = dd + (size_t)sa0 * 384 + sl0;
            const float* d1p = dd + (size_t)sa1 * 384 + sl1;
#pragma unroll
            for (int jd = 0; jd < 4; ++jd) {
                const int i0 = jd * 16 + 2 * c;
                float e00 = v0 ? __ldg(d0p + i0 * 6)       : 0.f;
                float e01 = v0 ? __ldg(d0p + (i0 + 1) * 6) : 0.f;
                float e02 = v0 ? __ldg(d0p + (i0 + 8) * 6) : 0.f;
                float e03 = v0 ? __ldg(d0p + (i0 + 9) * 6) : 0.f;
                float e10 = v1 ? __ldg(d1p + i0 * 6)       : 0.f;
                float e11 = v1 ? __ldg(d1p + (i0 + 1) * 6) : 0.f;
                float e12 = v1 ? __ldg(d1p + (i0 + 8) * 6) : 0.f;
                float e13 = v1 ? __ldg(d1p + (i0 + 9) * 6) : 0.f;
                split_pk(e00, e01, Ahd[jd][0], Ald[jd][0]);
                split_pk(e10, e11, Ahd[jd][1], Ald[jd][1]);
                split_pk(e02, e03, Ahd[jd][2], Ald[jd][2]);
                split_pk(e12, e13, Ahd[jd][3], Ald[jd][3]);
            }
        }

        float acc[8][4];
#pragma unroll
        for (int nt = 0; nt < 8; ++nt)
#pragma unroll
            for (int e = 0; e < 4; ++e) acc[nt][e] = 0.f;

        // ==== 3 chained layers: (Ah + Al) x B, 2-term fp16 ====
#pragma unroll
        for (int l = 0; l < 3; ++l) {
#pragma unroll
            for (int j = 0; j < 12; ++j) {
                const uint32_t* Ah = (j < 8) ? Ahx[j] : Ahd[j - 8];
                const uint32_t* Al = (j < 8) ? Alx[j] : Ald[j - 8];
                const uint4* bp = Bfr + ((l * 12 + j) * 4) * 32 + lane;
#pragma unroll
                for (int p = 0; p < 4; ++p) {
                    uint4 bh = bp[p * 32];
                    mma4(acc[2 * p],     Ah, bh.x, bh.y);
                    mma4(acc[2 * p + 1], Ah, bh.z, bh.w);
                    mma4(acc[2 * p],     Al, bh.x, bh.y);
                    mma4(acc[2 * p + 1], Al, bh.z, bh.w);
                }
            }
            if (l < 2) {
                // D -> next-layer d fragments, register-local (o dim == next k dim)
#pragma unroll
                for (int jd = 0; jd < 4; ++jd) {
                    const int o0 = jd * 16 + 2 * c;
                    float bb0 = bias[l * 64 + o0],     bb1 = bias[l * 64 + o0 + 1];
                    float bb8 = bias[l * 64 + o0 + 8], bb9 = bias[l * 64 + o0 + 9];
                    float t0 = fmaxf(acc[2 * jd][0] + bb0, 0.f);
                    float t1 = fmaxf(acc[2 * jd][1] + bb1, 0.f);
                    float t2 = fmaxf(acc[2 * jd][2] + bb0, 0.f);
                    float t3 = fmaxf(acc[2 * jd][3] + bb1, 0.f);
                    float u0 = fmaxf(acc[2 * jd + 1][0] + bb8, 0.f);
                    float u1 = fmaxf(acc[2 * jd + 1][1] + bb9, 0.f);
                    float u2 = fmaxf(acc[2 * jd + 1][2] + bb8, 0.f);
                    float u3 = fmaxf(acc[2 * jd + 1][3] + bb9, 0.f);
                    split_pk(t0, t1, Ahd[jd][0], Ald[jd][0]);
                    split_pk(t2, t3, Ahd[jd][1], Ald[jd][1]);
                    split_pk(u0, u1, Ahd[jd][2], Ald[jd][2]);
                    split_pk(u2, u3, Ahd[jd][3], Ald[jd][3]);
#pragma unroll
                    for (int e = 0; e < 4; ++e) {
                        acc[2 * jd][e] = 0.f;
                        acc[2 * jd + 1][e] = 0.f;
                    }
                }
            }
        }

        // ==== epilogue: acc+b3 -> warp smem transpose -> relu(+d1) -> gmem ====
        {
#pragma unroll
            for (int nt = 0; nt < 8; ++nt) {
                const int o0 = nt * 8 + 2 * c;
                const float bb0 = bias[128 + o0], bb1 = bias[128 + o0 + 1];
                eb[g * 68 + o0]           = acc[nt][0] + bb0;
                eb[g * 68 + o0 + 1]       = acc[nt][1] + bb1;
                eb[(g + 8) * 68 + o0]     = acc[nt][2] + bb0;
                eb[(g + 8) * 68 + o0 + 1] = acc[nt][3] + bb1;
            }
            __syncwarp();

            const int saA = (int)(row0 / 6);
            const int saB = (int)((row0 + 15) / 6);
            for (int sa = saA; sa <= saB; ++sa) {
                if (sa >= n) break;
                const int mb = (int)((long)sa * 6 - row0);   // row index of slot 0
                if (mb >= 0 && mb + 6 <= 16) {
                    // full sample: coalesced float4 path
                    const float* ddp = dd + (size_t)sa * 384;
                    float*       op  = out + (size_t)sa * 384;
#pragma unroll
                    for (int it = 0; it < 3; ++it) {
                        const int f = (it * 32 + lane) * 4;
                        float4 dv = __ldg((const float4*)(ddp + f));
                        float r[4];
#pragma unroll
                        for (int e = 0; e < 4; ++e) {
                            const int fe = f + e;
                            const int o  = fe / 6;
                            const int sl = fe - o * 6;
                            r[e] = eb[(mb + sl) * 68 + o];
                        }
                        float4 ov;
                        ov.x = fmaxf(r[0] + dv.x, 0.f);
                        ov.y = fmaxf(r[1] + dv.y, 0.f);
                        ov.z = fmaxf(r[2] + dv.z, 0.f);
                        ov.w = fmaxf(r[3] + dv.w, 0.f);
                        *(float4*)(op + f) = ov;
                    }
                } else {
                    // boundary sample: scalar path
#pragma unroll
                    for (int sl = 0; sl < 6; ++sl) {
                        const int m = mb + sl;
                        if (m < 0 || m >= 16) continue;
                        if (row0 + m >= rmax) continue;
#pragma unroll
                        for (int h = 0; h < 2; ++h) {
                            const int o = lane + 32 * h;
                            const size_t a = (size_t)sa * 384 + (size_t)o * 6 + sl;
                            out[a] = fmaxf(eb[m * 68 + o] + dd[a], 0.f);
                        }
                    }
                }
            }
            __syncwarp();   // eb reused next tile
        }
    }
}

extern "C" void kernel_launch(void* const* d_in, const int* in_sizes, int n_in,
                              void* d_out, int out_size) {
    const float* x  = (const float*)d_in[0];
    const float* dd = (const float*)d_in[1];
    const float* W1 = (const float*)d_in[2];
    const float* b1 = (const float*)d_in[3];
    const float* W2 = (const float*)d_in[4];
    const float* b2 = (const float*)d_in[5];
    const float* W3 = (const float*)d_in[6];
    const float* b3 = (const float*)d_in[7];
    float* out = (float*)d_out;

    const int n = in_sizes[0] / (ND * 12);

    int sms = 148;
    cudaDeviceGetAttribute(&sms, cudaDevAttrMultiProcessorCount, 0);
    cudaFuncSetAttribute(dijet_mma, cudaFuncAttributeMaxDynamicSharedMemorySize, SMEM_BYTES);

    dijet_mma<<<sms, THREADS, SMEM_BYTES>>>(x, dd, W1, b1, W2, b2, W3, b3, out, n);
}

// round 11
// speedup vs baseline: 1.7142x; 1.1513x over previous
#include <cuda_runtime.h>
#include <cuda_fp16.h>
#include <cstdint>

#define ND 64
#define THREADS 448
#define NWARP 14
#define TILE_R 224           // rows per CTA tile (14 warps x m16)

// ---- smem layout (bytes) ----
#define BF_OFF   0                    // uint4 [3 l][12 j][4 p][32 lane] = 73728
#define BIAS_OFF 73728                // 192 floats = 768
#define SCR_OFF  74496                // weight-staging bounce: 6144 floats = 24576 B
#define EPI_OFF  99072                // 14 warps * 16*68 floats = 60928 B
#define SMEM_BYTES (99072 + 60928)    // 160000

// fp32 -> (fp16 hi, fp16 lo) packed words
__device__ __forceinline__ void split_pk(float v0, float v1, uint32_t& hw, uint32_t& lw) {
    __half h0 = __float2half_rn(v0), h1 = __float2half_rn(v1);
    __half l0 = __float2half_rn(v0 - __half2float(h0));
    __half l1 = __float2half_rn(v1 - __half2float(h1));
    hw = (uint32_t)__half_as_ushort(h0) | ((uint32_t)__half_as_ushort(h1) << 16);
    lw = (uint32_t)__half_as_ushort(l0) | ((uint32_t)__half_as_ushort(l1) << 16);
}
__device__ __forceinline__ uint32_t pk_h(float v0, float v1) {
    __half h0 = __float2half_rn(v0), h1 = __float2half_rn(v1);
    return (uint32_t)__half_as_ushort(h0) | ((uint32_t)__half_as_ushort(h1) << 16);
}

__device__ __forceinline__ void mma4(float* c, const uint32_t* a, uint32_t b0, uint32_t b1) {
    asm volatile(
        "mma.sync.aligned.m16n8k16.row.col.f32.f16.f16.f32 "
        "{%0,%1,%2,%3}, {%4,%5,%6,%7}, {%8,%9}, {%0,%1,%2,%3};"
        : "+f"(c[0]), "+f"(c[1]), "+f"(c[2]), "+f"(c[3])
        : "r"(a[0]), "r"(a[1]), "r"(a[2]), "r"(a[3]), "r"(b0), "r"(b1));
}

__global__ __launch_bounds__(THREADS, 1)
void dijet_mma(const float* __restrict__ x, const float* __restrict__ dd,
               const float* __restrict__ W1, const float* __restrict__ b1,
               const float* __restrict__ W2, const float* __restrict__ b2,
               const float* __restrict__ W3, const float* __restrict__ b3,
               float* __restrict__ out, int n) {
    extern __shared__ char smem[];
    uint4*  Bfr  = (uint4*)(smem + BF_OFF);
    float*  bias = (float*)(smem + BIAS_OFF);
    float*  scr  = (float*)(smem + SCR_OFF);

    const int tid  = threadIdx.x;
    const int w    = tid >> 5;
    const int lane = tid & 31;
    const int g    = lane >> 2;     // row-in-frag 0..7
    const int c    = lane & 3;      // k/n sub-index

    float* eb = (float*)(smem + EPI_OFF) + w * (16 * 68);

    if (tid < 64) { bias[tid] = b1[tid]; bias[64 + tid] = b2[tid]; bias[128 + tid] = b3[tid]; }

    // ==== stage weights once: fp32 [o][i][k] -> single-fp16 fragments ====
    {
        const float* Wg[3] = {W1, W2, W3};
        for (int l = 0; l < 3; ++l) {
            for (int oh = 0; oh < 2; ++oh) {
                __syncthreads();
                const float4* src = (const float4*)(Wg[l] + oh * 32 * 192);
                float4* dst = (float4*)scr;
                for (int i4 = tid; i4 < 1536; i4 += THREADS) dst[i4] = src[i4];
                __syncthreads();
#pragma unroll
                for (int q = 0; q < 2; ++q) {
                    int cmb = w * 2 + q;            // 0..27, use 0..23
                    if (cmb < 24) {
                        int j = cmb >> 1, pp = cmb & 1, p = oh * 2 + pp;
                        int nl0 = pp * 16 + g, nl1 = nl0 + 8;
                        int k0 = j * 16 + 2 * c;
                        int blk = k0 >> 6, i0 = k0 & 63;
                        const float* s0p = scr + nl0 * 192 + blk;
                        const float* s1p = scr + nl1 * 192 + blk;
                        uint32_t h0 = pk_h(s0p[i0 * 3],       s0p[(i0 + 1) * 3]);
                        uint32_t h1 = pk_h(s0p[(i0 + 8) * 3], s0p[(i0 + 9) * 3]);
                        uint32_t h2 = pk_h(s1p[i0 * 3],       s1p[(i0 + 1) * 3]);
                        uint32_t h3 = pk_h(s1p[(i0 + 8) * 3], s1p[(i0 + 9) * 3]);
                        Bfr[((l * 12 + j) * 4 + p) * 32 + lane] = make_uint4(h0, h1, h2, h3);
                    }
                }
            }
        }
        __syncthreads();   // last barrier: Bfr/bias read-only from here on
    }

    const long rmax   = (long)n * 6;
    const int  ntiles = (int)((rmax + TILE_R - 1) / TILE_R);

    for (int tile = blockIdx.x; tile < ntiles; tile += gridDim.x) {
        const long base = (long)tile * TILE_R;
        const long row0 = base + w * 16;           // this warp's first row

        const long r0 = row0 + g;
        const long r1 = r0 + 8;
        const bool v0 = r0 < rmax, v1 = r1 < rmax;
        const int  sa0 = (int)(r0 / 6), sl0 = (int)(r0 - (long)sa0 * 6);
        const int  sa1 = (int)(r1 / 6), sl1 = (int)(r1 - (long)sa1 * 6);

        uint32_t Ahx[8][4], Ahd[4][4], Ald[4][4];

        // ==== direct gmem gather -> A fragments (x 1-term fp16) ====
        {
            const float* px0 = x + (size_t)sa0 * 768 + 2 * sl0;
            const float* px1 = x + (size_t)sa1 * 768 + 2 * sl1;
            const float2 z2 = make_float2(0.f, 0.f);
#pragma unroll
            for (int j = 0; j < 4; ++j) {
                const int i0 = j * 16 + 2 * c;
                float2 p00 = v0 ? __ldg((const float2*)(px0 + i0 * 12))       : z2;
                float2 p01 = v0 ? __ldg((const float2*)(px0 + (i0 + 1) * 12)) : z2;
                float2 p02 = v0 ? __ldg((const float2*)(px0 + (i0 + 8) * 12)) : z2;
                float2 p03 = v0 ? __ldg((const float2*)(px0 + (i0 + 9) * 12)) : z2;
                float2 p10 = v1 ? __ldg((const float2*)(px1 + i0 * 12))       : z2;
                float2 p11 = v1 ? __ldg((const float2*)(px1 + (i0 + 1) * 12)) : z2;
                float2 p12 = v1 ? __ldg((const float2*)(px1 + (i0 + 8) * 12)) : z2;
                float2 p13 = v1 ? __ldg((const float2*)(px1 + (i0 + 9) * 12)) : z2;
                Ahx[j][0]     = pk_h(p00.x, p01.x);
                Ahx[j][1]     = pk_h(p10.x, p11.x);
                Ahx[j][2]     = pk_h(p02.x, p03.x);
                Ahx[j][3]     = pk_h(p12.x, p13.x);
                Ahx[j + 4][0] = pk_h(p00.y, p01.y);
                Ahx[j + 4][1] = pk_h(p10.y, p11.y);
                Ahx[j + 4][2] = pk_h(p02.y, p03.y);
                Ahx[j + 4][3] = pk_h(p12.y, p13.y);
            }
            const float* d0p = dd + (size_t)sa0 * 384 + sl0;
            const float* d1p = dd + (size_t)sa1 * 384 + sl1;
#pragma unroll
            for (int jd = 0; jd < 4; ++jd) {
                const int i0 = jd * 16 + 2 * c;
                float e00 = v0 ? __ldg(d0p + i0 * 6)       : 0.f;
                float e01 = v0 ? __ldg(d0p + (i0 + 1) * 6) : 0.f;
                float e02 = v0 ? __ldg(d0p + (i0 + 8) * 6) : 0.f;
                float e03 = v0 ? __ldg(d0p + (i0 + 9) * 6) : 0.f;
                float e10 = v1 ? __ldg(d1p + i0 * 6)       : 0.f;
                float e11 = v1 ? __ldg(d1p + (i0 + 1) * 6) : 0.f;
                float e12 = v1 ? __ldg(d1p + (i0 + 8) * 6) : 0.f;
                float e13 = v1 ? __ldg(d1p + (i0 + 9) * 6) : 0.f;
                split_pk(e00, e01, Ahd[jd][0], Ald[jd][0]);
                split_pk(e10, e11, Ahd[jd][1], Ald[jd][1]);
                split_pk(e02, e03, Ahd[jd][2], Ald[jd][2]);
                split_pk(e12, e13, Ahd[jd][3], Ald[jd][3]);
            }
        }

        float acc[8][4];
#pragma unroll
        for (int nt = 0; nt < 8; ++nt)
#pragma unroll
            for (int e = 0; e < 4; ++e) acc[nt][e] = 0.f;

        // ==== 3 chained layers: x 1-term, d 2-term fp16 ====
#pragma unroll
        for (int l = 0; l < 3; ++l) {
#pragma unroll
            for (int j = 0; j < 8; ++j) {
                const uint4* bp = Bfr + ((l * 12 + j) * 4) * 32 + lane;
#pragma unroll
                for (int p = 0; p < 4; ++p) {
                    uint4 bh = bp[p * 32];
                    mma4(acc[2 * p],     Ahx[j], bh.x, bh.y);
                    mma4(acc[2 * p + 1], Ahx[j], bh.z, bh.w);
                }
            }
#pragma unroll
            for (int jd = 0; jd < 4; ++jd) {
                const uint4* bp = Bfr + ((l * 12 + 8 + jd) * 4) * 32 + lane;
#pragma unroll
                for (int p = 0; p < 4; ++p) {
                    uint4 bh = bp[p * 32];
                    mma4(acc[2 * p],     Ahd[jd], bh.x, bh.y);
                    mma4(acc[2 * p + 1], Ahd[jd], bh.z, bh.w);
                    mma4(acc[2 * p],     Ald[jd], bh.x, bh.y);
                    mma4(acc[2 * p + 1], Ald[jd], bh.z, bh.w);
                }
            }
            if (l < 2) {
                // D -> next-layer d fragments, register-local (o dim == next k dim)
#pragma unroll
                for (int jd = 0; jd < 4; ++jd) {
                    const int o0 = jd * 16 + 2 * c;
                    float bb0 = bias[l * 64 + o0],     bb1 = bias[l * 64 + o0 + 1];
                    float bb8 = bias[l * 64 + o0 + 8], bb9 = bias[l * 64 + o0 + 9];
                    float t0 = fmaxf(acc[2 * jd][0] + bb0, 0.f);
                    float t1 = fmaxf(acc[2 * jd][1] + bb1, 0.f);
                    float t2 = fmaxf(acc[2 * jd][2] + bb0, 0.f);
                    float t3 = fmaxf(acc[2 * jd][3] + bb1, 0.f);
                    float u0 = fmaxf(acc[2 * jd + 1][0] + bb8, 0.f);
                    float u1 = fmaxf(acc[2 * jd + 1][1] + bb9, 0.f);
                    float u2 = fmaxf(acc[2 * jd + 1][2] + bb8, 0.f);
                    float u3 = fmaxf(acc[2 * jd + 1][3] + bb9, 0.f);
                    split_pk(t0, t1, Ahd[jd][0], Ald[jd][0]);
                    split_pk(t2, t3, Ahd[jd][1], Ald[jd][1]);
                    split_pk(u0, u1, Ahd[jd][2], Ald[jd][2]);
                    split_pk(u2, u3, Ahd[jd][3], Ald[jd][3]);
#pragma unroll
                    for (int e = 0; e < 4; ++e) {
                        acc[2 * jd][e] = 0.f;
                        acc[2 * jd + 1][e] = 0.f;
                    }
                }
            }
        }

        // ==== epilogue: acc+b3 -> warp smem transpose -> relu(+d1) -> gmem ====
        {
#pragma unroll
            for (int nt = 0; nt < 8; ++nt) {
                const int o0 = nt * 8 + 2 * c;
                const float bb0 = bias[128 + o0], bb1 = bias[128 + o0 + 1];
                eb[g * 68 + o0]           = acc[nt][0] + bb0;
                eb[g * 68 + o0 + 1]       = acc[nt][1] + bb1;
                eb[(g + 8) * 68 + o0]     = acc[nt][2] + bb0;
                eb[(g + 8) * 68 + o0 + 1] = acc[nt][3] + bb1;
            }
            __syncwarp();

            const int saA = (int)(row0 / 6);
            const int saB = (int)((row0 + 15) / 6);
            for (int sa = saA; sa <= saB; ++sa) {
                if (sa >= n) break;
                const int mb = (int)((long)sa * 6 - row0);   // row index of slot 0
                if (mb >= 0 && mb + 6 <= 16) {
                    // full sample: coalesced float4 path
                    const float* ddp = dd + (size_t)sa * 384;
                    float*       op  = out + (size_t)sa * 384;
#pragma unroll
                    for (int it = 0; it < 3; ++it) {
                        const int f = (it * 32 + lane) * 4;
                        float4 dv = __ldg((const float4*)(ddp + f));
                        float r[4];
#pragma unroll
                        for (int e = 0; e < 4; ++e) {
                            const int fe = f + e;
                            const int o  = fe / 6;
                            const int sl = fe - o * 6;
                            r[e] = eb[(mb + sl) * 68 + o];
                        }
                        float4 ov;
                        ov.x = fmaxf(r[0] + dv.x, 0.f);
                        ov.y = fmaxf(r[1] + dv.y, 0.f);
                        ov.z = fmaxf(r[2] + dv.z, 0.f);
                        ov.w = fmaxf(r[3] + dv.w, 0.f);
                        *(float4*)(op + f) = ov;
                    }
                } else {
                    // boundary sample: scalar path
#pragma unroll
                    for (int sl = 0; sl < 6; ++sl) {
                        const int m = mb + sl;
                        if (m < 0 || m >= 16) continue;
                        if (row0 + m >= rmax) continue;
#pragma unroll
                        for (int h = 0; h < 2; ++h) {
                            const int o = lane + 32 * h;
                            const size_t a = (size_t)sa * 384 + (size_t)o * 6 + sl;
                            out[a] = fmaxf(eb[m * 68 + o] + dd[a], 0.f);
                        }
                    }
                }
            }
            __syncwarp();   // eb reused next tile
        }
    }
}

extern "C" void kernel_launch(void* const* d_in, const int* in_sizes, int n_in,
                              void* d_out, int out_size) {
    const float* x  = (const float*)d_in[0];
    const float* dd = (const float*)d_in[1];
    const float* W1 = (const float*)d_in[2];
    const float* b1 = (const float*)d_in[3];
    const float* W2 = (const float*)d_in[4];
    const float* b2 = (const float*)d_in[5];
    const float* W3 = (const float*)d_in[6];
    const float* b3 = (const float*)d_in[7];
    float* out = (float*)d_out;

    const int n = in_sizes[0] / (ND * 12);

    int sms = 148;
    cudaDeviceGetAttribute(&sms, cudaDevAttrMultiProcessorCount, 0);
    cudaFuncSetAttribute(dijet_mma, cudaFuncAttributeMaxDynamicSharedMemorySize, SMEM_BYTES);

    dijet_mma<<<sms, THREADS, SMEM_BYTES>>>(x, dd, W1, b1, W2, b2, W3, b3, out, n);
}

// round 12
// speedup vs baseline: 2.0713x; 1.2083x over previous
#include <cuda_runtime.h>
#include <cuda_fp16.h>
#include <cstdint>

#define ND 64
#define THREADS 512
#define TILE_R 256           // rows per CTA tile (16 warps x m16)

// ---- smem layout (bytes) ----
#define BF_OFF   0                    // uint4 [3 l][12 j][4 p][32 lane] = 73728
#define BIAS_OFF 73728                // 192 floats = 768
#define SCR_OFF  74496                // weight-staging bounce: 6144 floats = 24576 B
#define EPI_OFF  99072                // 16 warps * 16*68 floats = 69632 B
#define SMEM_BYTES (99072 + 69632)    // 168704

// fp32 -> (fp16 hi, fp16 lo) packed words
__device__ __forceinline__ void split_pk(float v0, float v1, uint32_t& hw, uint32_t& lw) {
    __half h0 = __float2half_rn(v0), h1 = __float2half_rn(v1);
    __half l0 = __float2half_rn(v0 - __half2float(h0));
    __half l1 = __float2half_rn(v1 - __half2float(h1));
    hw = (uint32_t)__half_as_ushort(h0) | ((uint32_t)__half_as_ushort(h1) << 16);
    lw = (uint32_t)__half_as_ushort(l0) | ((uint32_t)__half_as_ushort(l1) << 16);
}
__device__ __forceinline__ uint32_t pk_h(float v0, float v1) {
    __half h0 = __float2half_rn(v0), h1 = __float2half_rn(v1);
    return (uint32_t)__half_as_ushort(h0) | ((uint32_t)__half_as_ushort(h1) << 16);
}

__device__ __forceinline__ void mma4(float* c, const uint32_t* a, uint32_t b0, uint32_t b1) {
    asm volatile(
        "mma.sync.aligned.m16n8k16.row.col.f32.f16.f16.f32 "
        "{%0,%1,%2,%3}, {%4,%5,%6,%7}, {%8,%9}, {%0,%1,%2,%3};"
        : "+f"(c[0]), "+f"(c[1]), "+f"(c[2]), "+f"(c[3])
        : "r"(a[0]), "r"(a[1]), "r"(a[2]), "r"(a[3]), "r"(b0), "r"(b1));
}

__global__ __launch_bounds__(THREADS, 1)
void dijet_mma(const float* __restrict__ x, const float* __restrict__ dd,
               const float* __restrict__ W1, const float* __restrict__ b1,
               const float* __restrict__ W2, const float* __restrict__ b2,
               const float* __restrict__ W3, const float* __restrict__ b3,
               float* __restrict__ out, int n) {
    extern __shared__ char smem[];
    uint4*  Bfr  = (uint4*)(smem + BF_OFF);
    float*  bias = (float*)(smem + BIAS_OFF);
    float*  scr  = (float*)(smem + SCR_OFF);

    const int tid  = threadIdx.x;
    const int w    = tid >> 5;
    const int lane = tid & 31;
    const int g    = lane >> 2;     // row-in-frag 0..7
    const int c    = lane & 3;      // k/n sub-index

    float* eb = (float*)(smem + EPI_OFF) + w * (16 * 68);

    if (tid < 64) { bias[tid] = b1[tid]; bias[64 + tid] = b2[tid]; bias[128 + tid] = b3[tid]; }

    // ==== stage weights once: fp32 [o][i][k] -> single-fp16 fragments ====
    {
        const float* Wg[3] = {W1, W2, W3};
        for (int l = 0; l < 3; ++l) {
            for (int oh = 0; oh < 2; ++oh) {
                __syncthreads();
                const float4* src = (const float4*)(Wg[l] + oh * 32 * 192);
                float4* dst = (float4*)scr;
                for (int i4 = tid; i4 < 1536; i4 += THREADS) dst[i4] = src[i4];
                __syncthreads();
                {
                    int cmb = w;                    // 0..15, use 0..11 (j), 2 p per warp
                    if (cmb < 12) {
                        int j = cmb;
#pragma unroll
                        for (int pp = 0; pp < 2; ++pp) {
                            int p = oh * 2 + pp;
                            int nl0 = pp * 16 + g, nl1 = nl0 + 8;
                            int k0 = j * 16 + 2 * c;
                            int blk = k0 >> 6, i0 = k0 & 63;
                            const float* s0p = scr + nl0 * 192 + blk;
                            const float* s1p = scr + nl1 * 192 + blk;
                            uint32_t h0 = pk_h(s0p[i0 * 3],       s0p[(i0 + 1) * 3]);
                            uint32_t h1 = pk_h(s0p[(i0 + 8) * 3], s0p[(i0 + 9) * 3]);
                            uint32_t h2 = pk_h(s1p[i0 * 3],       s1p[(i0 + 1) * 3]);
                            uint32_t h3 = pk_h(s1p[(i0 + 8) * 3], s1p[(i0 + 9) * 3]);
                            Bfr[((l * 12 + j) * 4 + p) * 32 + lane] = make_uint4(h0, h1, h2, h3);
                        }
                    }
                }
            }
        }
        __syncthreads();   // last barrier: Bfr/bias read-only from here on
    }

    const long rmax   = (long)n * 6;
    const int  ntiles = (int)((rmax + TILE_R - 1) / TILE_R);

    for (int tile = blockIdx.x; tile < ntiles; tile += gridDim.x) {
        const long base = (long)tile * TILE_R;
        const long row0 = base + w * 16;           // this warp's first row

        const long r0 = row0 + g;
        const long r1 = r0 + 8;
        const bool v0 = r0 < rmax, v1 = r1 < rmax;
        const int  sa0 = (int)(r0 / 6), sl0 = (int)(r0 - (long)sa0 * 6);
        const int  sa1 = (int)(r1 / 6), sl1 = (int)(r1 - (long)sa1 * 6);

        uint32_t Ahx[8][4], Ahd[4][4];

        // ==== direct gmem gather -> A fragments (all 1-term fp16) ====
        {
            const float* px0 = x + (size_t)sa0 * 768 + 2 * sl0;
            const float* px1 = x + (size_t)sa1 * 768 + 2 * sl1;
            const float2 z2 = make_float2(0.f, 0.f);
#pragma unroll
            for (int j = 0; j < 4; ++j) {
                const int i0 = j * 16 + 2 * c;
                float2 p00 = v0 ? __ldg((const float2*)(px0 + i0 * 12))       : z2;
                float2 p01 = v0 ? __ldg((const float2*)(px0 + (i0 + 1) * 12)) : z2;
                float2 p02 = v0 ? __ldg((const float2*)(px0 + (i0 + 8) * 12)) : z2;
                float2 p03 = v0 ? __ldg((const float2*)(px0 + (i0 + 9) * 12)) : z2;
                float2 p10 = v1 ? __ldg((const float2*)(px1 + i0 * 12))       : z2;
                float2 p11 = v1 ? __ldg((const float2*)(px1 + (i0 + 1) * 12)) : z2;
                float2 p12 = v1 ? __ldg((const float2*)(px1 + (i0 + 8) * 12)) : z2;
                float2 p13 = v1 ? __ldg((const float2*)(px1 + (i0 + 9) * 12)) : z2;
                Ahx[j][0]     = pk_h(p00.x, p01.x);
                Ahx[j][1]     = pk_h(p10.x, p11.x);
                Ahx[j][2]     = pk_h(p02.x, p03.x);
                Ahx[j][3]     = pk_h(p12.x, p13.x);
                Ahx[j + 4][0] = pk_h(p00.y, p01.y);
                Ahx[j + 4][1] = pk_h(p10.y, p11.y);
                Ahx[j + 4][2] = pk_h(p02.y, p03.y);
                Ahx[j + 4][3] = pk_h(p12.y, p13.y);
            }
            const float* d0p = dd + (size_t)sa0 * 384 + sl0;
            const float* d1p = dd + (size_t)sa1 * 384 + sl1;
#pragma unroll
            for (int jd = 0; jd < 4; ++jd) {
                const int i0 = jd * 16 + 2 * c;
                float e00 = v0 ? __ldg(d0p + i0 * 6)       : 0.f;
                float e01 = v0 ? __ldg(d0p + (i0 + 1) * 6) : 0.f;
                float e02 = v0 ? __ldg(d0p + (i0 + 8) * 6) : 0.f;
                float e03 = v0 ? __ldg(d0p + (i0 + 9) * 6) : 0.f;
                float e10 = v1 ? __ldg(d1p + i0 * 6)       : 0.f;
                float e11 = v1 ? __ldg(d1p + (i0 + 1) * 6) : 0.f;
                float e12 = v1 ? __ldg(d1p + (i0 + 8) * 6) : 0.f;
                float e13 = v1 ? __ldg(d1p + (i0 + 9) * 6) : 0.f;
                Ahd[jd][0] = pk_h(e00, e01);
                Ahd[jd][1] = pk_h(e10, e11);
                Ahd[jd][2] = pk_h(e02, e03);
                Ahd[jd][3] = pk_h(e12, e13);
            }
        }

        float acc[8][4];
#pragma unroll
        for (int nt = 0; nt < 8; ++nt)
#pragma unroll
            for (int e = 0; e < 4; ++e) acc[nt][e] = 0.f;

        // ==== 3 chained layers: all 1-term fp16 ====
#pragma unroll
        for (int l = 0; l < 3; ++l) {
#pragma unroll
            for (int j = 0; j < 8; ++j) {
                const uint4* bp = Bfr + ((l * 12 + j) * 4) * 32 + lane;
#pragma unroll
                for (int p = 0; p < 4; ++p) {
                    uint4 bh = bp[p * 32];
                    mma4(acc[2 * p],     Ahx[j], bh.x, bh.y);
                    mma4(acc[2 * p + 1], Ahx[j], bh.z, bh.w);
                }
            }
#pragma unroll
            for (int jd = 0; jd < 4; ++jd) {
                const uint4* bp = Bfr + ((l * 12 + 8 + jd) * 4) * 32 + lane;
#pragma unroll
                for (int p = 0; p < 4; ++p) {
                    uint4 bh = bp[p * 32];
                    mma4(acc[2 * p],     Ahd[jd], bh.x, bh.y);
                    mma4(acc[2 * p + 1], Ahd[jd], bh.z, bh.w);
                }
            }
            if (l < 2) {
                // D -> next-layer d fragments, register-local (o dim == next k dim)
#pragma unroll
                for (int jd = 0; jd < 4; ++jd) {
                    const int o0 = jd * 16 + 2 * c;
                    float bb0 = bias[l * 64 + o0],     bb1 = bias[l * 64 + o0 + 1];
                    float bb8 = bias[l * 64 + o0 + 8], bb9 = bias[l * 64 + o0 + 9];
                    Ahd[jd][0] = pk_h(fmaxf(acc[2 * jd][0] + bb0, 0.f),
                                      fmaxf(acc[2 * jd][1] + bb1, 0.f));
                    Ahd[jd][1] = pk_h(fmaxf(acc[2 * jd][2] + bb0, 0.f),
                                      fmaxf(acc[2 * jd][3] + bb1, 0.f));
                    Ahd[jd][2] = pk_h(fmaxf(acc[2 * jd + 1][0] + bb8, 0.f),
                                      fmaxf(acc[2 * jd + 1][1] + bb9, 0.f));
                    Ahd[jd][3] = pk_h(fmaxf(acc[2 * jd + 1][2] + bb8, 0.f),
                                      fmaxf(acc[2 * jd + 1][3] + bb9, 0.f));
#pragma unroll
                    for (int e = 0; e < 4; ++e) {
                        acc[2 * jd][e] = 0.f;
                        acc[2 * jd + 1][e] = 0.f;
                    }
                }
            }
        }

        // ==== epilogue: acc+b3 -> warp smem transpose -> relu(+d1) -> gmem ====
        {
#pragma unroll
            for (int nt = 0; nt < 8; ++nt) {
                const int o0 = nt * 8 + 2 * c;
                const float bb0 = bias[128 + o0], bb1 = bias[128 + o0 + 1];
                eb[g * 68 + o0]           = acc[nt][0] + bb0;
                eb[g * 68 + o0 + 1]       = acc[nt][1] + bb1;
                eb[(g + 8) * 68 + o0]     = acc[nt][2] + bb0;
                eb[(g + 8) * 68 + o0 + 1] = acc[nt][3] + bb1;
            }
            __syncwarp();

            const int saA = (int)(row0 / 6);
            const int saB = (int)((row0 + 15) / 6);
            for (int sa = saA; sa <= saB; ++sa) {
                if (sa >= n) break;
                const int mb = (int)((long)sa * 6 - row0);   // row index of slot 0
                if (mb >= 0 && mb + 6 <= 16) {
                    // full sample: coalesced float4 path
                    const float* ddp = dd + (size_t)sa * 384;
                    float*       op  = out + (size_t)sa * 384;
#pragma unroll
                    for (int it = 0; it < 3; ++it) {
                        const int f = (it * 32 + lane) * 4;
                        float4 dv = __ldg((const float4*)(ddp + f));
                        float r[4];
#pragma unroll
                        for (int e = 0; e < 4; ++e) {
                            const int fe = f + e;
                            const int o  = fe / 6;
                            const int sl = fe - o * 6;
                            r[e] = eb[(mb + sl) * 68 + o];
                        }
                        float4 ov;
                        ov.x = fmaxf(r[0] + dv.x, 0.f);
                        ov.y = fmaxf(r[1] + dv.y, 0.f);
                        ov.z = fmaxf(r[2] + dv.z, 0.f);
                        ov.w = fmaxf(r[3] + dv.w, 0.f);
                        *(float4*)(op + f) = ov;
                    }
                } else {
                    // boundary sample: scalar path
#pragma unroll
                    for (int sl = 0; sl < 6; ++sl) {
                        const int m = mb + sl;
                        if (m < 0 || m >= 16) continue;
                        if (row0 + m >= rmax) continue;
#pragma unroll
                        for (int h = 0; h < 2; ++h) {
                            const int o = lane + 32 * h;
                            const size_t a = (size_t)sa * 384 + (size_t)o * 6 + sl;
                            out[a] = fmaxf(eb[m * 68 + o] + dd[a], 0.f);
                        }
                    }
                }
            }
            __syncwarp();   // eb reused next tile
        }
    }
}

extern "C" void kernel_launch(void* const* d_in, const int* in_sizes, int n_in,
                              void* d_out, int out_size) {
    const float* x  = (const float*)d_in[0];
    const float* dd = (const float*)d_in[1];
    const float* W1 = (const float*)d_in[2];
    const float* b1 = (const float*)d_in[3];
    const float* W2 = (const float*)d_in[4];
    const float* b2 = (const float*)d_in[5];
    const float* W3 = (const float*)d_in[6];
    const float* b3 = (const float*)d_in[7];
    float* out = (float*)d_out;

    const int n = in_sizes[0] / (ND * 12);

    int sms = 148;
    cudaDeviceGetAttribute(&sms, cudaDevAttrMultiProcessorCount, 0);
    cudaFuncSetAttribute(dijet_mma, cudaFuncAttributeMaxDynamicSharedMemorySize, SMEM_BYTES);

    dijet_mma<<<sms, THREADS, SMEM_BYTES>>>(x, dd, W1, b1, W2, b2, W3, b3, out, n);
}